// round 14
// baseline (speedup 1.0000x reference)
#include <cuda_runtime.h>
#include <cstdint>
#include <math.h>

#define D_DIM 300
#define ROW_BYTES (D_DIM * 16)             // 4800 B
#define PAIR_BYTES (2 * ROW_BYTES)         // 9600 B: V row + W row
#define VOCAB_SZ 50000
#define BUCKET_SHIFT 4
#define NBUCK (VOCAB_SZ >> BUCKET_SHIFT)
#define MAX_B (1 << 20)
#define SCAN_T 1024
#define SCAN_PER ((NBUCK + SCAN_T - 1) / SCAN_T)
#define WARPS_CTA 5
#define PPW 4                               // pairs per warp
#define SMEM_BYTES (WARPS_CTA * 2 * PAIR_BYTES + WARPS_CTA * 16)

__device__ int g_counts[NBUCK];
__device__ int g_perm[MAX_B];

// ---------------- lean bucket-sort pipeline (proven) ----------------

__global__ void count_kernel(const int* __restrict__ IJ, int B) {
    int p = blockIdx.x * blockDim.x + threadIdx.x;
    if (p < B) atomicAdd(&g_counts[__ldg(IJ + 2 * p) >> BUCKET_SHIFT], 1);
}

__global__ void scan_kernel() {
    __shared__ int sums[SCAN_T];
    const int t = threadIdx.x;
    const int base = t * SCAN_PER;
    int local[SCAN_PER];
    int tot = 0;
#pragma unroll
    for (int e = 0; e < SCAN_PER; e++) {
        int idx = base + e;
        local[e] = (idx < NBUCK) ? g_counts[idx] : 0;
        tot += local[e];
    }
    sums[t] = tot;
    __syncthreads();
    for (int off = 1; off < SCAN_T; off <<= 1) {
        int v = (t >= off) ? sums[t - off] : 0;
        __syncthreads();
        sums[t] += v;
        __syncthreads();
    }
    int running = (t == 0) ? 0 : sums[t - 1];
#pragma unroll
    for (int e = 0; e < SCAN_PER; e++) {
        int idx = base + e;
        if (idx < NBUCK) { g_counts[idx] = running; running += local[e]; }
    }
}

__global__ void scatter_kernel(const int* __restrict__ IJ, int B) {
    int p = blockIdx.x * blockDim.x + threadIdx.x;
    if (p < B) {
        int b = __ldg(IJ + 2 * p) >> BUCKET_SHIFT;
        int pos = atomicAdd(&g_counts[b], 1);
        g_perm[pos] = p;
    }
}

// ---------------- main kernel: double-buffered bulk-async pipeline ----------------

__device__ __forceinline__ uint32_t smem_u32(const void* p) {
    uint32_t a;
    asm("{ .reg .u64 t; cvta.to.shared.u64 t, %1; cvt.u32.u64 %0, t; }" : "=r"(a) : "l"(p));
    return a;
}

__device__ __forceinline__ void mbar_wait(uint32_t mb, uint32_t parity) {
    uint32_t done;
    asm volatile(
        "{\n\t.reg .pred P;\n\t"
        "mbarrier.try_wait.parity.acquire.cta.shared::cta.b64 P, [%1], %2;\n\t"
        "selp.b32 %0, 1, 0, P;\n\t}"
        : "=r"(done) : "r"(mb), "r"(parity) : "memory");
    if (!done) {
        asm volatile(
            "{\n\t.reg .pred P;\n\t"
            "WL_%=:\n\t"
            "mbarrier.try_wait.parity.acquire.cta.shared::cta.b64 P, [%0], %1, 0x989680;\n\t"
            "@P bra.uni WD_%=;\n\t"
            "bra.uni WL_%=;\n\t"
            "WD_%=:\n\t}"
            :: "r"(mb), "r"(parity) : "memory");
    }
}

__device__ __forceinline__ void fma16(float* acc, const float4 w, const float4 v) {
    acc[0]  = fmaf(w.x, v.x, acc[0]);
    acc[1]  = fmaf(w.x, v.y, acc[1]);
    acc[2]  = fmaf(w.x, v.z, acc[2]);
    acc[3]  = fmaf(w.x, v.w, acc[3]);
    acc[4]  = fmaf(w.y, v.x, acc[4]);
    acc[5]  = fmaf(w.y, v.y, acc[5]);
    acc[6]  = fmaf(w.y, v.z, acc[6]);
    acc[7]  = fmaf(w.y, v.w, acc[7]);
    acc[8]  = fmaf(w.z, v.x, acc[8]);
    acc[9]  = fmaf(w.z, v.y, acc[9]);
    acc[10] = fmaf(w.z, v.z, acc[10]);
    acc[11] = fmaf(w.z, v.w, acc[11]);
    acc[12] = fmaf(w.w, v.x, acc[12]);
    acc[13] = fmaf(w.w, v.y, acc[13]);
    acc[14] = fmaf(w.w, v.z, acc[14]);
    acc[15] = fmaf(w.w, v.w, acc[15]);
}

__global__ __launch_bounds__(WARPS_CTA * 32)
void multisense_kernel(const char* __restrict__ Vb,
                       const char* __restrict__ Wb,
                       const float4* __restrict__ vb4,
                       const float4* __restrict__ wb4,
                       const int* __restrict__ IJ,
                       float* __restrict__ out,
                       int B)
{
    extern __shared__ char smem[];
    const int wid  = threadIdx.x >> 5;
    const int lane = threadIdx.x & 31;

    char* mybuf = smem + wid * (2 * PAIR_BYTES);                     // [2][PAIR_BYTES]
    uint64_t* mymbar = (uint64_t*)(smem + WARPS_CTA * 2 * PAIR_BYTES) + wid * 2;
    const uint32_t mb0  = smem_u32(&mymbar[0]);
    const uint32_t mb1  = smem_u32(&mymbar[1]);
    const uint32_t sbase = smem_u32(mybuf);

    const long long base = (long long)(blockIdx.x * WARPS_CTA + wid) * PPW;
    if (base >= B) return;

    if (lane == 0) {
        asm volatile("mbarrier.init.shared.b64 [%0], 1;" :: "r"(mb0) : "memory");
        asm volatile("mbarrier.init.shared.b64 [%0], 1;" :: "r"(mb1) : "memory");
        asm volatile("fence.proxy.async.shared::cta;" ::: "memory");
    }
    __syncwarp();

    // lane 0 tracks current/next pair indices
    int pcur = 0, icur = 0, jcur = 0;
    if (lane == 0) {
        pcur = __ldg(g_perm + base);
        icur = __ldg(IJ + 2 * pcur);
        jcur = __ldg(IJ + 2 * pcur + 1);
        // prefetch pair 0 into buffer 0
        asm volatile("mbarrier.arrive.expect_tx.shared.b64 _, [%0], %1;"
                     :: "r"(mb0), "r"((uint32_t)PAIR_BYTES) : "memory");
        const char* vsrc = Vb + (long long)icur * ROW_BYTES;
        const char* wsrc = Wb + (long long)jcur * ROW_BYTES;
        asm volatile("cp.async.bulk.shared::cta.global.mbarrier::complete_tx::bytes [%0], [%1], %2, [%3];"
                     :: "r"(sbase), "l"(vsrc), "r"((uint32_t)ROW_BYTES), "r"(mb0) : "memory");
        asm volatile("cp.async.bulk.shared::cta.global.mbarrier::complete_tx::bytes [%0], [%1], %2, [%3];"
                     :: "r"(sbase + ROW_BYTES), "l"(wsrc), "r"((uint32_t)ROW_BYTES), "r"(mb0) : "memory");
    }

    uint32_t phase[2] = {0u, 0u};

#pragma unroll 1
    for (int k = 0; k < PPW; k++) {
        const long long pr = base + k;
        if (pr >= B) break;

        int pnext = 0, inext = 0, jnext = 0;
        const bool have_next = (pr + 1 < B) && (k + 1 < PPW);
        if (lane == 0 && have_next) {
            // prefetch pair k+1 into the other buffer (free: compute k-1 done)
            pnext = __ldg(g_perm + pr + 1);
            inext = __ldg(IJ + 2 * pnext);
            jnext = __ldg(IJ + 2 * pnext + 1);
            const uint32_t nb = ((k + 1) & 1);
            const uint32_t mbn = nb ? mb1 : mb0;
            const uint32_t dst = sbase + nb * PAIR_BYTES;
            asm volatile("mbarrier.arrive.expect_tx.shared.b64 _, [%0], %1;"
                         :: "r"(mbn), "r"((uint32_t)PAIR_BYTES) : "memory");
            const char* vsrc = Vb + (long long)inext * ROW_BYTES;
            const char* wsrc = Wb + (long long)jnext * ROW_BYTES;
            asm volatile("cp.async.bulk.shared::cta.global.mbarrier::complete_tx::bytes [%0], [%1], %2, [%3];"
                         :: "r"(dst), "l"(vsrc), "r"((uint32_t)ROW_BYTES), "r"(mbn) : "memory");
            asm volatile("cp.async.bulk.shared::cta.global.mbarrier::complete_tx::bytes [%0], [%1], %2, [%3];"
                         :: "r"(dst + ROW_BYTES), "l"(wsrc), "r"((uint32_t)ROW_BYTES), "r"(mbn) : "memory");
        }

        // wait for pair k's data
        const uint32_t cb = (k & 1);
        mbar_wait(cb ? mb1 : mb0, phase[cb]);
        phase[cb] ^= 1u;

        const float4* __restrict__ Vs = (const float4*)(mybuf + cb * PAIR_BYTES);
        const float4* __restrict__ Ws = (const float4*)(mybuf + cb * PAIR_BYTES + ROW_BYTES);

        float acc[16];
#pragma unroll
        for (int q = 0; q < 16; q++) acc[q] = 0.0f;

#pragma unroll 1
        for (int q = 0; q < 9; q++) {
            const int d = lane + 32 * q;
            fma16(acc, Ws[d], Vs[d]);
        }
        if (lane < 12) {
            const int d = lane + 288;
            fma16(acc, Ws[d], Vs[d]);
        }

#pragma unroll
        for (int off = 16; off > 0; off >>= 1) {
#pragma unroll
            for (int q = 0; q < 16; q++)
                acc[q] += __shfl_xor_sync(0xffffffffu, acc[q], off);
        }

        if (lane == 0) {
            const float4 wb = __ldg(wb4 + jcur);
            const float4 vb = __ldg(vb4 + icur);
            const float bs[4] = {wb.x, wb.y, wb.z, wb.w};
            const float bt[4] = {vb.x, vb.y, vb.z, vb.w};
            float vals[16];
            float m = -INFINITY;
#pragma unroll
            for (int s = 0; s < 4; s++)
#pragma unroll
                for (int t = 0; t < 4; t++) {
                    const float x = acc[s * 4 + t] + bs[s] + bt[t];
                    vals[s * 4 + t] = x;
                    m = fmaxf(m, x);
                }
            float sum = 0.0f;
#pragma unroll
            for (int q = 0; q < 16; q++)
                sum += __expf(vals[q] - m);
            out[pcur] = __logf(sum) + m;

            pcur = pnext; icur = inext; jcur = jnext;
        }
    }
}

extern "C" void kernel_launch(void* const* d_in, const int* in_sizes, int n_in,
                              void* d_out, int out_size)
{
    const char* Vb        = (const char*)d_in[0];
    const char* Wb        = (const char*)d_in[1];
    const float4* vb4     = (const float4*)d_in[2];
    const float4* wb4     = (const float4*)d_in[3];
    const int* IJ         = (const int*)d_in[4];
    float* out            = (float*)d_out;

    const int B = in_sizes[4] / 2;

    void* counts_ptr = nullptr;
    cudaGetSymbolAddress(&counts_ptr, g_counts);
    cudaMemsetAsync(counts_ptr, 0, NBUCK * sizeof(int), 0);

    const int t = 256;
    count_kernel<<<(B + t - 1) / t, t>>>(IJ, B);
    scan_kernel<<<1, SCAN_T>>>();
    scatter_kernel<<<(B + t - 1) / t, t>>>(IJ, B);

    cudaFuncSetAttribute(multisense_kernel,
                         cudaFuncAttributeMaxDynamicSharedMemorySize, SMEM_BYTES);
    const int pairs_per_cta = WARPS_CTA * PPW;
    const int blocks = (B + pairs_per_cta - 1) / pairs_per_cta;
    multisense_kernel<<<blocks, WARPS_CTA * 32, SMEM_BYTES>>>(Vb, Wb, vb4, wb4, IJ, out, B);
}

// round 15
// speedup vs baseline: 1.3433x; 1.3433x over previous
#include <cuda_runtime.h>
#include <cstdint>
#include <math.h>

#define D_DIM 300
#define ROW_BYTES (D_DIM * 16)
#define VOCAB_SZ 50000
#define BUCKET_SHIFT 4
#define NBUCK (VOCAB_SZ >> BUCKET_SHIFT)
#define MAX_B (1 << 20)
#define SCAN_T 1024
#define SCAN_PER ((NBUCK + SCAN_T - 1) / SCAN_T)
#define WARPS_CTA 8
#define STAGES 3
#define NITER 10                       // ceil(300/32)

__device__ int g_counts[NBUCK];
__device__ int g_perm[MAX_B];

// ---------------- lean bucket-sort pipeline (proven in R12) ----------------

__global__ void count_kernel(const int* __restrict__ IJ, int B) {
    int p = blockIdx.x * blockDim.x + threadIdx.x;
    if (p < B) atomicAdd(&g_counts[__ldg(IJ + 2 * p) >> BUCKET_SHIFT], 1);
}

__global__ void scan_kernel() {
    __shared__ int sums[SCAN_T];
    const int t = threadIdx.x;
    const int base = t * SCAN_PER;
    int local[SCAN_PER];
    int tot = 0;
#pragma unroll
    for (int e = 0; e < SCAN_PER; e++) {
        int idx = base + e;
        local[e] = (idx < NBUCK) ? g_counts[idx] : 0;
        tot += local[e];
    }
    sums[t] = tot;
    __syncthreads();
    for (int off = 1; off < SCAN_T; off <<= 1) {
        int v = (t >= off) ? sums[t - off] : 0;
        __syncthreads();
        sums[t] += v;
        __syncthreads();
    }
    int running = (t == 0) ? 0 : sums[t - 1];
#pragma unroll
    for (int e = 0; e < SCAN_PER; e++) {
        int idx = base + e;
        if (idx < NBUCK) { g_counts[idx] = running; running += local[e]; }
    }
}

__global__ void scatter_kernel(const int* __restrict__ IJ, int B) {
    int p = blockIdx.x * blockDim.x + threadIdx.x;
    if (p < B) {
        int b = __ldg(IJ + 2 * p) >> BUCKET_SHIFT;
        int pos = atomicAdd(&g_counts[b], 1);
        g_perm[pos] = p;
    }
}

// ---------------- main kernel: cp.async 3-stage pipeline, high occupancy ----------------

__device__ __forceinline__ uint32_t smem_u32(const void* p) {
    uint32_t a;
    asm("{ .reg .u64 t; cvta.to.shared.u64 t, %1; cvt.u32.u64 %0, t; }" : "=r"(a) : "l"(p));
    return a;
}

__device__ __forceinline__ void fma16(float* acc, const float4 w, const float4 v) {
    acc[0]  = fmaf(w.x, v.x, acc[0]);
    acc[1]  = fmaf(w.x, v.y, acc[1]);
    acc[2]  = fmaf(w.x, v.z, acc[2]);
    acc[3]  = fmaf(w.x, v.w, acc[3]);
    acc[4]  = fmaf(w.y, v.x, acc[4]);
    acc[5]  = fmaf(w.y, v.y, acc[5]);
    acc[6]  = fmaf(w.y, v.z, acc[6]);
    acc[7]  = fmaf(w.y, v.w, acc[7]);
    acc[8]  = fmaf(w.z, v.x, acc[8]);
    acc[9]  = fmaf(w.z, v.y, acc[9]);
    acc[10] = fmaf(w.z, v.z, acc[10]);
    acc[11] = fmaf(w.z, v.w, acc[11]);
    acc[12] = fmaf(w.w, v.x, acc[12]);
    acc[13] = fmaf(w.w, v.y, acc[13]);
    acc[14] = fmaf(w.w, v.z, acc[14]);
    acc[15] = fmaf(w.w, v.w, acc[15]);
}

// stage chunk: 512B V + 512B W per warp per stage
__global__ __launch_bounds__(WARPS_CTA * 32)
void multisense_kernel(const char* __restrict__ Vb,
                       const char* __restrict__ Wb,
                       const float4* __restrict__ vb4,
                       const float4* __restrict__ wb4,
                       const int* __restrict__ IJ,
                       float* __restrict__ out,
                       int B)
{
    __shared__ alignas(16) char stage[WARPS_CTA][STAGES][1024];

    const int wid  = threadIdx.x >> 5;
    const int lane = threadIdx.x & 31;
    const int warp_id = blockIdx.x * WARPS_CTA + wid;
    if (warp_id >= B) return;

    const int p = __ldg(g_perm + warp_id);
    const int i = __ldg(IJ + 2 * p);
    const int j = __ldg(IJ + 2 * p + 1);

    const char* __restrict__ vrow = Vb + (long long)i * ROW_BYTES;
    const char* __restrict__ wrow = Wb + (long long)j * ROW_BYTES;

    uint32_t sb[STAGES];
#pragma unroll
    for (int s = 0; s < STAGES; s++)
        sb[s] = smem_u32(&stage[wid][s][0]) + lane * 16;

    // issue chunk k into stage k%STAGES (predicated on d<300), always commit a group
    auto issue = [&](int k) {
        const int d = lane + 32 * k;
        if (k < NITER && d < D_DIM) {
            const uint32_t vdst = sb[k % STAGES];
            const uint32_t wdst = vdst + 512;
            const char* vsrc = vrow + (size_t)d * 16;
            const char* wsrc = wrow + (size_t)d * 16;
            asm volatile("cp.async.cg.shared.global [%0], [%1], 16;" :: "r"(vdst), "l"(vsrc) : "memory");
            asm volatile("cp.async.cg.shared.global [%0], [%1], 16;" :: "r"(wdst), "l"(wsrc) : "memory");
        }
        asm volatile("cp.async.commit_group;" ::: "memory");
    };

    issue(0); issue(1); issue(2);

    float acc[16];
#pragma unroll
    for (int k = 0; k < 16; k++) acc[k] = 0.0f;

#pragma unroll
    for (int k = 0; k < NITER; k++) {
        // at this point committed = k+3 groups; keep ≤2 pending => group k done
        asm volatile("cp.async.wait_group %0;" :: "n"(STAGES - 1) : "memory");
        const int d = lane + 32 * k;
        if (d < D_DIM) {
            const float4 v = *(const float4*)(&stage[wid][k % STAGES][lane * 16]);
            const float4 w = *(const float4*)(&stage[wid][k % STAGES][512 + lane * 16]);
            fma16(acc, w, v);
        }
        issue(k + STAGES);   // commits empty group when k+STAGES >= NITER
    }

    // Warp butterfly reduction (proven correct)
#pragma unroll
    for (int off = 16; off > 0; off >>= 1) {
#pragma unroll
        for (int k = 0; k < 16; k++)
            acc[k] += __shfl_xor_sync(0xffffffffu, acc[k], off);
    }

    if (lane == 0) {
        const float4 wb = __ldg(wb4 + j);
        const float4 vb = __ldg(vb4 + i);
        const float bs[4] = {wb.x, wb.y, wb.z, wb.w};
        const float bt[4] = {vb.x, vb.y, vb.z, vb.w};

        float vals[16];
        float m = -INFINITY;
#pragma unroll
        for (int s = 0; s < 4; s++)
#pragma unroll
            for (int t = 0; t < 4; t++) {
                const float x = acc[s * 4 + t] + bs[s] + bt[t];
                vals[s * 4 + t] = x;
                m = fmaxf(m, x);
            }
        float sum = 0.0f;
#pragma unroll
        for (int k = 0; k < 16; k++)
            sum += __expf(vals[k] - m);
        out[p] = __logf(sum) + m;
    }
}

extern "C" void kernel_launch(void* const* d_in, const int* in_sizes, int n_in,
                              void* d_out, int out_size)
{
    const char* Vb        = (const char*)d_in[0];
    const char* Wb        = (const char*)d_in[1];
    const float4* vb4     = (const float4*)d_in[2];
    const float4* wb4     = (const float4*)d_in[3];
    const int* IJ         = (const int*)d_in[4];
    float* out            = (float*)d_out;

    const int B = in_sizes[4] / 2;

    void* counts_ptr = nullptr;
    cudaGetSymbolAddress(&counts_ptr, g_counts);
    cudaMemsetAsync(counts_ptr, 0, NBUCK * sizeof(int), 0);

    const int t = 256;
    count_kernel<<<(B + t - 1) / t, t>>>(IJ, B);
    scan_kernel<<<1, SCAN_T>>>();
    scatter_kernel<<<(B + t - 1) / t, t>>>(IJ, B);

    const int blocks = (B + WARPS_CTA - 1) / WARPS_CTA;
    multisense_kernel<<<blocks, WARPS_CTA * 32>>>(Vb, Wb, vb4, wb4, IJ, out, B);
}